// round 14
// baseline (speedup 1.0000x reference)
#include <cuda_runtime.h>
#include <cuda_fp16.h>
#include <math.h>

#define NN   20000
#define EMAX 320000
#define FDIM 512
#define NH   4
#define HC   128
#define DCAP 256

#define OFF_W0   0
#define OFF_RW0  131072
#define OFF_W1   262144
#define OFF_W2   524288
#define WH_TOT   786432

// ---------------- scratch ----------------------------------------------------
__device__ __half sc_gh[(size_t)NN * FDIM];
__device__ float  sc_a[(size_t)NN * FDIM];
__device__ float  sc_b[(size_t)NN * FDIM];
__device__ __half sc_xh[(size_t)NN * 256];
__device__ __half sc_h1h[(size_t)NN * FDIM];
__device__ __half sc_h2h[(size_t)NN * FDIM];
__device__ __half sc_wh[WH_TOT];
__device__ float  sc_es[NN * NH];
__device__ float  sc_ed[NN * NH];
__device__ int    sc_deg[NN];
__device__ int    sc_rowptr[NN + 1];
__device__ int    sc_cursor[NN];
__device__ int    sc_csr[EMAX + NN];
__device__ int    sc_is64;

__device__ __forceinline__ float* pick_rw(int sel, float* ext) {
    if (sel == 0) return ext;
    if (sel == 1) return sc_a;
    return sc_b;
}
__device__ __forceinline__ const float* pick_ro(int sel, const float* ext) {
    if (sel == 0) return ext;
    if (sel == 1) return sc_a;
    return sc_b;
}
__device__ __forceinline__ const __half* pick_ah(int sel) {
    if (sel == 0) return sc_xh;
    if (sel == 1) return sc_h1h;
    return sc_h2h;
}
__device__ __forceinline__ int load_edge(const void* ei, size_t idx) {
    if (sc_is64) return (int)((const long long*)ei)[idx];
    return ((const int*)ei)[idx];
}

// ---------------- dtype probe -------------------------------------------------
__global__ void detect_k(const void* ei) {
    const int* p = (const int*)ei;
    int any = 0;
#pragma unroll 8
    for (int i = 0; i < 256; i++) any |= p[2 * i + 1];
    sc_is64 = (any == 0) ? 1 : 0;
}

// ---------------- fp32 -> fp16 conversion -------------------------------------
__global__ void cvt_x_k(const float* __restrict__ x) {
    int stride = gridDim.x * blockDim.x;
    for (int i = blockIdx.x * blockDim.x + threadIdx.x; i < NN * 128; i += stride) {
        float2 v = *(const float2*)(x + 2 * (size_t)i);
        *(__half2*)(sc_xh + 2 * (size_t)i) = __floats2half2_rn(v.x, v.y);
    }
}
__global__ void cvt_w_k(const float* __restrict__ w0, const float* __restrict__ rw0,
                        const float* __restrict__ w1, const float* __restrict__ w2) {
    int stride = gridDim.x * blockDim.x;
    for (int i = blockIdx.x * blockDim.x + threadIdx.x; i < WH_TOT / 2; i += stride) {
        int e = 2 * i;
        float2 v;
        if (e < OFF_RW0)      v = *(const float2*)(w0 + e);
        else if (e < OFF_W1)  v = *(const float2*)(rw0 + (e - OFF_RW0));
        else if (e < OFF_W2)  v = *(const float2*)(w1 + (e - OFF_W1));
        else                  v = *(const float2*)(w2 + (e - OFF_W2));
        *(__half2*)(sc_wh + e) = __floats2half2_rn(v.x, v.y);
    }
}

// ---------------- CSR build ---------------------------------------------------
__global__ void init_deg_k() {
    int i = blockIdx.x * blockDim.x + threadIdx.x;
    if (i < NN) sc_deg[i] = 1;
}
__global__ void hist_k(const void* ei, int E) {
    int e = blockIdx.x * blockDim.x + threadIdx.x;
    if (e < E) atomicAdd(&sc_deg[load_edge(ei, (size_t)E + e)], 1);
}
__global__ void scan_k() {
    __shared__ int sums[1024];
    const int CH = 20;
    int t = threadIdx.x;
    int base = t * CH;
    int local[CH];
    int s = 0;
#pragma unroll
    for (int i = 0; i < CH; i++) {
        int idx = base + i;
        int v = (idx < NN) ? sc_deg[idx] : 0;
        local[i] = s;
        s += v;
    }
    sums[t] = s;
    __syncthreads();
    for (int off = 1; off < 1024; off <<= 1) {
        int v = (t >= off) ? sums[t - off] : 0;
        __syncthreads();
        sums[t] += v;
        __syncthreads();
    }
    int offset = (t == 0) ? 0 : sums[t - 1];
#pragma unroll
    for (int i = 0; i < CH; i++) {
        int idx = base + i;
        if (idx < NN) {
            int r = offset + local[i];
            sc_rowptr[idx] = r;
            sc_cursor[idx] = r;
        }
    }
    if (t == 1023) sc_rowptr[NN] = sums[1023];
}
__global__ void scatter_k(const void* ei, int E) {
    int i = blockIdx.x * blockDim.x + threadIdx.x;
    if (i < E) {
        int d = load_edge(ei, (size_t)E + i);
        int s = load_edge(ei, i);
        sc_csr[atomicAdd(&sc_cursor[d], 1)] = s;
    } else if (i < E + NN) {
        int v = i - E;
        sc_csr[atomicAdd(&sc_cursor[v], 1)] = v;
    }
}

// ---------------- FP16 GEMM (round-11 proven version: ld+sts+ldmatrix) -------
#define GBM 128
#define GBN 128
#define GBK 32
#define AH_LD 40
#define BH_LD 136

__device__ __forceinline__ void mma_f16(float* d, const unsigned* a, const unsigned* b) {
    asm volatile(
        "mma.sync.aligned.m16n8k16.row.col.f32.f16.f16.f32 "
        "{%0,%1,%2,%3}, {%4,%5,%6,%7}, {%8,%9}, {%0,%1,%2,%3};"
        : "+f"(d[0]), "+f"(d[1]), "+f"(d[2]), "+f"(d[3])
        : "r"(a[0]), "r"(a[1]), "r"(a[2]), "r"(a[3]), "r"(b[0]), "r"(b[1]));
}
__device__ __forceinline__ void ldsm_x4(unsigned* r, unsigned addr) {
    asm volatile("ldmatrix.sync.aligned.m8n8.x4.shared.b16 {%0,%1,%2,%3}, [%4];"
                 : "=r"(r[0]), "=r"(r[1]), "=r"(r[2]), "=r"(r[3]) : "r"(addr));
}
__device__ __forceinline__ void ldsm_x4_t(unsigned* r, unsigned addr) {
    asm volatile("ldmatrix.sync.aligned.m8n8.x4.trans.shared.b16 {%0,%1,%2,%3}, [%4];"
                 : "=r"(r[0]), "=r"(r[1]), "=r"(r[2]), "=r"(r[3]) : "r"(addr));
}

__global__ __launch_bounds__(256, 1) void tgemm_k(int asel, int woff,
                                                  int csel, int mode,
                                                  const float* __restrict__ avS,
                                                  const float* __restrict__ avD,
                                                  int M, int K) {
    const __half* A = pick_ah(asel);
    const __half* B = sc_wh + woff;

    __shared__ __half As[GBM][AH_LD];
    __shared__ __half Bs[GBK][BH_LD];
    __shared__ float es_sh[GBM];
    __shared__ float ed_sh[GBM];

    int tid  = threadIdx.x;
    int lane = tid & 31;
    int warp = tid >> 5;
    int wm = (warp >> 2) * 64;
    int wn = (warp & 3) * 32;
    int bm = blockIdx.y * GBM;
    int bn = blockIdx.x * GBN;

    if (mode && tid < GBM) { es_sh[tid] = 0.f; ed_sh[tid] = 0.f; }

    int aRow = tid >> 3;
    int aCol = (tid & 7) * 4;
    int bRow = tid >> 5;
    int bCol = (tid & 31) * 4;

    float acc[4][4][4];
#pragma unroll
    for (int i = 0; i < 4; i++)
#pragma unroll
        for (int j = 0; j < 4; j++)
#pragma unroll
            for (int q = 0; q < 4; q++) acc[i][j][q] = 0.f;

    uint2 ra[4], rb[4];
    int nk = K / GBK;

#pragma unroll
    for (int i = 0; i < 4; i++) {
        int r = aRow + 32 * i;
        ra[i] = (bm + r < M) ? *(const uint2*)(A + (size_t)(bm + r) * K + aCol)
                             : make_uint2(0u, 0u);
        rb[i] = *(const uint2*)(B + (size_t)(bRow + 8 * i) * FDIM + bn + bCol);
    }

    int a_lrow = lane & 15;
    int a_lcol = (lane >> 4) * 8;
    int g      = lane >> 3;
    int b_lrow = (g & 1) * 8 + (lane & 7);
    int b_lcol = (g >> 1) * 8;

    for (int kt = 0; kt < nk; kt++) {
#pragma unroll
        for (int i = 0; i < 4; i++) {
            *(uint2*)&As[aRow + 32 * i][aCol] = ra[i];
            *(uint2*)&Bs[bRow + 8 * i][bCol] = rb[i];
        }
        __syncthreads();

        if (kt + 1 < nk) {
            int kb = (kt + 1) * GBK;
#pragma unroll
            for (int i = 0; i < 4; i++) {
                int r = aRow + 32 * i;
                ra[i] = (bm + r < M)
                      ? *(const uint2*)(A + (size_t)(bm + r) * K + kb + aCol)
                      : make_uint2(0u, 0u);
                rb[i] = *(const uint2*)(B + (size_t)(kb + bRow + 8 * i) * FDIM + bn + bCol);
            }
        }

#pragma unroll
        for (int kk = 0; kk < GBK; kk += 16) {
            unsigned afr[4][4], bfr[4][2];
#pragma unroll
            for (int mt = 0; mt < 4; mt++) {
                unsigned ad = (unsigned)__cvta_generic_to_shared(
                    &As[wm + mt * 16 + a_lrow][kk + a_lcol]);
                ldsm_x4(afr[mt], ad);
            }
#pragma unroll
            for (int np = 0; np < 2; np++) {
                unsigned btmp[4];
                unsigned bd = (unsigned)__cvta_generic_to_shared(
                    &Bs[kk + b_lrow][wn + np * 16 + b_lcol]);
                ldsm_x4_t(btmp, bd);
                bfr[np * 2 + 0][0] = btmp[0];
                bfr[np * 2 + 0][1] = btmp[1];
                bfr[np * 2 + 1][0] = btmp[2];
                bfr[np * 2 + 1][1] = btmp[3];
            }
#pragma unroll
            for (int mt = 0; mt < 4; mt++)
#pragma unroll
                for (int nt = 0; nt < 4; nt++)
                    mma_f16(acc[mt][nt], afr[mt], bfr[nt]);
        }
        __syncthreads();
    }

    if (mode == 0) {
        float* C = pick_rw(csel, nullptr);
#pragma unroll
        for (int mt = 0; mt < 4; mt++) {
#pragma unroll
            for (int nt = 0; nt < 4; nt++) {
                int r = bm + wm + mt * 16 + (lane >> 2);
                int c = bn + wn + nt * 8 + (lane & 3) * 2;
                if (r < M)
                    *(float2*)(C + (size_t)r * FDIM + c) =
                        make_float2(acc[mt][nt][0], acc[mt][nt][1]);
                if (r + 8 < M)
                    *(float2*)(C + (size_t)(r + 8) * FDIM + c) =
                        make_float2(acc[mt][nt][2], acc[mt][nt][3]);
            }
        }
    } else {
        float asv[8], adv[8];
#pragma unroll
        for (int nt = 0; nt < 4; nt++)
#pragma unroll
            for (int p = 0; p < 2; p++) {
                int c = bn + wn + nt * 8 + (lane & 3) * 2 + p;
                asv[nt * 2 + p] = avS[c];
                adv[nt * 2 + p] = avD[c];
            }

        float s1[8], s2[8];
#pragma unroll
        for (int i = 0; i < 8; i++) { s1[i] = 0.f; s2[i] = 0.f; }

#pragma unroll
        for (int mt = 0; mt < 4; mt++) {
#pragma unroll
            for (int nt = 0; nt < 4; nt++) {
                int r = bm + wm + mt * 16 + (lane >> 2);
                int c = bn + wn + nt * 8 + (lane & 3) * 2;
                if (r < M)
                    *(__half2*)(sc_gh + (size_t)r * FDIM + c) =
                        __floats2half2_rn(acc[mt][nt][0], acc[mt][nt][1]);
                if (r + 8 < M)
                    *(__half2*)(sc_gh + (size_t)(r + 8) * FDIM + c) =
                        __floats2half2_rn(acc[mt][nt][2], acc[mt][nt][3]);
#pragma unroll
                for (int q = 0; q < 4; q++) {
                    int qh = q >> 1, p = q & 1;
                    s1[mt * 2 + qh] += acc[mt][nt][q] * asv[nt * 2 + p];
                    s2[mt * 2 + qh] += acc[mt][nt][q] * adv[nt * 2 + p];
                }
            }
        }
#pragma unroll
        for (int off = 1; off <= 2; off <<= 1)
#pragma unroll
            for (int i = 0; i < 8; i++) {
                s1[i] += __shfl_xor_sync(0xffffffffu, s1[i], off);
                s2[i] += __shfl_xor_sync(0xffffffffu, s2[i], off);
            }
        if ((lane & 3) == 0) {
#pragma unroll
            for (int mt = 0; mt < 4; mt++)
#pragma unroll
                for (int qh = 0; qh < 2; qh++) {
                    int rl = wm + mt * 16 + (lane >> 2) + 8 * qh;
                    atomicAdd(&es_sh[rl], s1[mt * 2 + qh]);
                    atomicAdd(&ed_sh[rl], s2[mt * 2 + qh]);
                }
        }
        __syncthreads();
        if (tid < GBM) {
            int r = bm + tid;
            if (r < M) {
                sc_es[r * NH + blockIdx.x] = es_sh[tid];
                sc_ed[r * NH + blockIdx.x] = ed_sh[tid];
            }
        }
    }
}

// ---------------- fused softmax + aggregate (256 thr, 2 warps/head) ----------
__global__ __launch_bounds__(256) void agg_k(const float* __restrict__ bias,
                                             int rsel,
                                             float* __restrict__ outext,
                                             int osel, int hsel) {
    const float* res = pick_ro(rsel, nullptr);
    float* out = pick_rw(osel, outext);
    __half* outh = (hsel == 1) ? sc_h1h : (hsel == 2) ? sc_h2h : nullptr;

    __shared__ float w_sh[NH][DCAP];
    __shared__ int   idx_sh[DCAP];
    __shared__ float inv_sh[NH];

    int d = blockIdx.x;
    int warp = threadIdx.x >> 5, lane = threadIdx.x & 31;
    int head = warp >> 1, half = warp & 1;
    int beg = sc_rowptr[d], end = sc_rowptr[d + 1];
    int deg = end - beg;

    if (deg <= DCAP) {
        if (half == 0) {
            float edv = sc_ed[d * NH + head];
            float m = -INFINITY;
            for (int j = lane; j < deg; j += 32) {
                int s = sc_csr[beg + j];
                if (warp == 0) idx_sh[j] = s;
                float e = sc_es[s * NH + head] + edv;
                e = e > 0.f ? e : 0.2f * e;
                w_sh[head][j] = e;
                m = fmaxf(m, e);
            }
#pragma unroll
            for (int o = 16; o; o >>= 1) m = fmaxf(m, __shfl_xor_sync(0xffffffffu, m, o));
            float den = 0.f;
            for (int j = lane; j < deg; j += 32) {
                float ex = __expf(w_sh[head][j] - m);
                w_sh[head][j] = ex;
                den += ex;
            }
#pragma unroll
            for (int o = 16; o; o >>= 1) den += __shfl_xor_sync(0xffffffffu, den, o);
            if (lane == 0) inv_sh[head] = 1.f / (den + 1e-16f);
        }
        __syncthreads();

        float inv = inv_sh[head];
        float2 acc = make_float2(0.f, 0.f);
        const __half* ghp = sc_gh + head * HC + half * 64 + 2 * lane;
#pragma unroll 8
        for (int j = 0; j < deg; j++) {
            int s = idx_sh[j];
            float wt = w_sh[head][j] * inv;
            unsigned hv = *(const unsigned*)(ghp + (size_t)s * FDIM);
            float2 f = __half22float2(*(const __half2*)&hv);
            acc.x += wt * f.x;
            acc.y += wt * f.y;
        }

        int c = head * HC + half * 64 + 2 * lane;
        float2 bv = *(const float2*)(bias + c);
        float2 rv = *(const float2*)(res + (size_t)d * FDIM + c);
        float2 o;
        o.x = fmaxf(acc.x + bv.x + rv.x, 0.f);
        o.y = fmaxf(acc.y + bv.y + rv.y, 0.f);
        *(float2*)(out + (size_t)d * FDIM + c) = o;
        if (outh) *(__half2*)(outh + (size_t)d * FDIM + c) = __floats2half2_rn(o.x, o.y);
    } else {
        float edv = sc_ed[d * NH + head];
        float m = -INFINITY;
        for (int j = beg + lane; j < end; j += 32) {
            int s = sc_csr[j];
            float e = sc_es[s * NH + head] + edv;
            e = e > 0.f ? e : 0.2f * e;
            m = fmaxf(m, e);
        }
#pragma unroll
        for (int o = 16; o; o >>= 1) m = fmaxf(m, __shfl_xor_sync(0xffffffffu, m, o));
        float den = 0.f;
        for (int j = beg + lane; j < end; j += 32) {
            int s = sc_csr[j];
            float e = sc_es[s * NH + head] + edv;
            e = e > 0.f ? e : 0.2f * e;
            den += __expf(e - m);
        }
#pragma unroll
        for (int o = 16; o; o >>= 1) den += __shfl_xor_sync(0xffffffffu, den, o);
        float inv = 1.f / (den + 1e-16f);

        float2 acc = make_float2(0.f, 0.f);
        const __half* ghp = sc_gh + head * HC + half * 64 + 2 * lane;
        for (int j = beg; j < end; j++) {
            int s = sc_csr[j];
            float e = sc_es[s * NH + head] + edv;
            e = e > 0.f ? e : 0.2f * e;
            float wt = __expf(e - m) * inv;
            unsigned hv = *(const unsigned*)(ghp + (size_t)s * FDIM);
            float2 f = __half22float2(*(const __half2*)&hv);
            acc.x += wt * f.x;
            acc.y += wt * f.y;
        }
        int c = head * HC + half * 64 + 2 * lane;
        float2 bv = *(const float2*)(bias + c);
        float2 rv = *(const float2*)(res + (size_t)d * FDIM + c);
        float2 o;
        o.x = fmaxf(acc.x + bv.x + rv.x, 0.f);
        o.y = fmaxf(acc.y + bv.y + rv.y, 0.f);
        *(float2*)(out + (size_t)d * FDIM + c) = o;
        if (outh) *(__half2*)(outh + (size_t)d * FDIM + c) = __floats2half2_rn(o.x, o.y);
    }
}

// ---------------- host orchestration ----------------------------------------
extern "C" void kernel_launch(void* const* d_in, const int* in_sizes, int n_in,
                              void* d_out, int out_size) {
    const float* x       = (const float*)d_in[0];
    const void* ei       = d_in[1];
    const float* w0      = (const float*)d_in[2];
    const float* b0      = (const float*)d_in[3];
    const float* asrc0   = (const float*)d_in[4];
    const float* adst0   = (const float*)d_in[5];
    const float* res_w0  = (const float*)d_in[6];
    const float* w1      = (const float*)d_in[7];
    const float* b1      = (const float*)d_in[8];
    const float* asrc1   = (const float*)d_in[9];
    const float* adst1   = (const float*)d_in[10];
    const float* w2      = (const float*)d_in[11];
    const float* b2      = (const float*)d_in[12];
    const float* asrc2   = (const float*)d_in[13];
    const float* adst2   = (const float*)d_in[14];
    float* out           = (float*)d_out;

    int E = in_sizes[1] / 2;

    static cudaStream_t s2 = nullptr;
    static cudaEvent_t evFork = nullptr, evJoin = nullptr;
    if (s2 == nullptr) {
        cudaStreamCreateWithFlags(&s2, cudaStreamNonBlocking);
        cudaEventCreateWithFlags(&evFork, cudaEventDisableTiming);
        cudaEventCreateWithFlags(&evJoin, cudaEventDisableTiming);
    }

    cudaEventRecord(evFork, 0);
    cudaStreamWaitEvent(s2, evFork, 0);
    detect_k<<<1, 1, 0, s2>>>(ei);
    init_deg_k<<<(NN + 255) / 256, 256, 0, s2>>>();
    hist_k<<<(E + 255) / 256, 256, 0, s2>>>(ei, E);
    scan_k<<<1, 1024, 0, s2>>>();
    scatter_k<<<(E + NN + 255) / 256, 256, 0, s2>>>(ei, E);
    cudaEventRecord(evJoin, s2);

    cvt_x_k<<<2048, 256>>>(x);
    cvt_w_k<<<1024, 256>>>(w0, res_w0, w1, w2);

    dim3 ggrid(FDIM / GBN, (NN + GBM - 1) / GBM);

    tgemm_k<<<ggrid, 256>>>(0, OFF_W0, 0, 1, asrc0, adst0, NN, 256);
    tgemm_k<<<ggrid, 256>>>(0, OFF_RW0, 2, 0, nullptr, nullptr, NN, 256);

    cudaStreamWaitEvent(0, evJoin, 0);
    agg_k<<<NN, 256>>>(b0, /*res=*/2, nullptr, /*out=*/1, /*h=*/1);

    tgemm_k<<<ggrid, 256>>>(1, OFF_W1, 0, 1, asrc1, adst1, NN, 512);
    agg_k<<<NN, 256>>>(b1, /*res=*/1, nullptr, /*out=*/2, /*h=*/2);

    tgemm_k<<<ggrid, 256>>>(2, OFF_W2, 0, 1, asrc2, adst2, NN, 512);
    agg_k<<<NN, 256>>>(b2, /*res=*/2, out, /*out=*/0, /*h=*/0);
}

// round 15
// speedup vs baseline: 1.1091x; 1.1091x over previous
#include <cuda_runtime.h>
#include <cuda_fp16.h>
#include <math.h>

#define NN   20000
#define EMAX 320000
#define FDIM 512
#define NH   4
#define HC   128
#define DCAP 256

#define OFF_W0   0
#define OFF_RW0  131072
#define OFF_W1   262144
#define OFF_W2   524288
#define WH_TOT   786432

// ---------------- scratch ----------------------------------------------------
__device__ __half sc_gh[(size_t)NN * FDIM];
__device__ float  sc_a[(size_t)NN * FDIM];
__device__ float  sc_b[(size_t)NN * FDIM];
__device__ __half sc_xh[(size_t)NN * 256];
__device__ __half sc_h1h[(size_t)NN * FDIM];
__device__ __half sc_h2h[(size_t)NN * FDIM];
__device__ __half sc_wh[WH_TOT];
__device__ float  sc_es[NN * NH];
__device__ float  sc_ed[NN * NH];
__device__ int    sc_deg[NN];
__device__ int    sc_rowptr[NN + 1];
__device__ int    sc_cursor[NN];
__device__ int    sc_csr[EMAX + NN];
__device__ int    sc_is64;

__device__ __forceinline__ float* pick_rw(int sel, float* ext) {
    if (sel == 0) return ext;
    if (sel == 1) return sc_a;
    return sc_b;
}
__device__ __forceinline__ const float* pick_ro(int sel, const float* ext) {
    if (sel == 0) return ext;
    if (sel == 1) return sc_a;
    return sc_b;
}
__device__ __forceinline__ const __half* pick_ah(int sel) {
    if (sel == 0) return sc_xh;
    if (sel == 1) return sc_h1h;
    return sc_h2h;
}
__device__ __forceinline__ int load_edge(const void* ei, size_t idx) {
    if (sc_is64) return (int)((const long long*)ei)[idx];
    return ((const int*)ei)[idx];
}

// ---------------- dtype probe -------------------------------------------------
__global__ void detect_k(const void* ei) {
    const int* p = (const int*)ei;
    int any = 0;
#pragma unroll 8
    for (int i = 0; i < 256; i++) any |= p[2 * i + 1];
    sc_is64 = (any == 0) ? 1 : 0;
}

// ---------------- fp32 -> fp16 conversion -------------------------------------
__global__ void cvt_x_k(const float* __restrict__ x) {
    int stride = gridDim.x * blockDim.x;
    for (int i = blockIdx.x * blockDim.x + threadIdx.x; i < NN * 128; i += stride) {
        float2 v = *(const float2*)(x + 2 * (size_t)i);
        *(__half2*)(sc_xh + 2 * (size_t)i) = __floats2half2_rn(v.x, v.y);
    }
}
__global__ void cvt_w_k(const float* __restrict__ w0, const float* __restrict__ rw0,
                        const float* __restrict__ w1, const float* __restrict__ w2) {
    int stride = gridDim.x * blockDim.x;
    for (int i = blockIdx.x * blockDim.x + threadIdx.x; i < WH_TOT / 2; i += stride) {
        int e = 2 * i;
        float2 v;
        if (e < OFF_RW0)      v = *(const float2*)(w0 + e);
        else if (e < OFF_W1)  v = *(const float2*)(rw0 + (e - OFF_RW0));
        else if (e < OFF_W2)  v = *(const float2*)(w1 + (e - OFF_W1));
        else                  v = *(const float2*)(w2 + (e - OFF_W2));
        *(__half2*)(sc_wh + e) = __floats2half2_rn(v.x, v.y);
    }
}

// ---------------- CSR build ---------------------------------------------------
__global__ void init_deg_k() {
    int i = blockIdx.x * blockDim.x + threadIdx.x;
    if (i < NN) sc_deg[i] = 1;
}
__global__ void hist_k(const void* ei, int E) {
    int e = blockIdx.x * blockDim.x + threadIdx.x;
    if (e < E) atomicAdd(&sc_deg[load_edge(ei, (size_t)E + e)], 1);
}
__global__ void scan_k() {
    __shared__ int sums[1024];
    const int CH = 20;
    int t = threadIdx.x;
    int base = t * CH;
    int local[CH];
    int s = 0;
#pragma unroll
    for (int i = 0; i < CH; i++) {
        int idx = base + i;
        int v = (idx < NN) ? sc_deg[idx] : 0;
        local[i] = s;
        s += v;
    }
    sums[t] = s;
    __syncthreads();
    for (int off = 1; off < 1024; off <<= 1) {
        int v = (t >= off) ? sums[t - off] : 0;
        __syncthreads();
        sums[t] += v;
        __syncthreads();
    }
    int offset = (t == 0) ? 0 : sums[t - 1];
#pragma unroll
    for (int i = 0; i < CH; i++) {
        int idx = base + i;
        if (idx < NN) {
            int r = offset + local[i];
            sc_rowptr[idx] = r;
            sc_cursor[idx] = r;
        }
    }
    if (t == 1023) sc_rowptr[NN] = sums[1023];
}
__global__ void scatter_k(const void* ei, int E) {
    int i = blockIdx.x * blockDim.x + threadIdx.x;
    if (i < E) {
        int d = load_edge(ei, (size_t)E + i);
        int s = load_edge(ei, i);
        sc_csr[atomicAdd(&sc_cursor[d], 1)] = s;
    } else if (i < E + NN) {
        int v = i - E;
        sc_csr[atomicAdd(&sc_cursor[v], 1)] = v;
    }
}

// ---------------- FP16 GEMM (round-11 proven version: ld+sts+ldmatrix) -------
#define GBM 128
#define GBN 128
#define GBK 32
#define AH_LD 40
#define BH_LD 136

__device__ __forceinline__ void mma_f16(float* d, const unsigned* a, const unsigned* b) {
    asm volatile(
        "mma.sync.aligned.m16n8k16.row.col.f32.f16.f16.f32 "
        "{%0,%1,%2,%3}, {%4,%5,%6,%7}, {%8,%9}, {%0,%1,%2,%3};"
        : "+f"(d[0]), "+f"(d[1]), "+f"(d[2]), "+f"(d[3])
        : "r"(a[0]), "r"(a[1]), "r"(a[2]), "r"(a[3]), "r"(b[0]), "r"(b[1]));
}
__device__ __forceinline__ void ldsm_x4(unsigned* r, unsigned addr) {
    asm volatile("ldmatrix.sync.aligned.m8n8.x4.shared.b16 {%0,%1,%2,%3}, [%4];"
                 : "=r"(r[0]), "=r"(r[1]), "=r"(r[2]), "=r"(r[3]) : "r"(addr));
}
__device__ __forceinline__ void ldsm_x4_t(unsigned* r, unsigned addr) {
    asm volatile("ldmatrix.sync.aligned.m8n8.x4.trans.shared.b16 {%0,%1,%2,%3}, [%4];"
                 : "=r"(r[0]), "=r"(r[1]), "=r"(r[2]), "=r"(r[3]) : "r"(addr));
}

__global__ __launch_bounds__(256, 1) void tgemm_k(int asel, int woff,
                                                  int csel, int mode,
                                                  const float* __restrict__ avS,
                                                  const float* __restrict__ avD,
                                                  int M, int K) {
    const __half* A = pick_ah(asel);
    const __half* B = sc_wh + woff;

    __shared__ __half As[GBM][AH_LD];
    __shared__ __half Bs[GBK][BH_LD];
    __shared__ float es_sh[GBM];
    __shared__ float ed_sh[GBM];

    int tid  = threadIdx.x;
    int lane = tid & 31;
    int warp = tid >> 5;
    int wm = (warp >> 2) * 64;
    int wn = (warp & 3) * 32;
    int bm = blockIdx.y * GBM;
    int bn = blockIdx.x * GBN;

    if (mode && tid < GBM) { es_sh[tid] = 0.f; ed_sh[tid] = 0.f; }

    int aRow = tid >> 3;
    int aCol = (tid & 7) * 4;
    int bRow = tid >> 5;
    int bCol = (tid & 31) * 4;

    float acc[4][4][4];
#pragma unroll
    for (int i = 0; i < 4; i++)
#pragma unroll
        for (int j = 0; j < 4; j++)
#pragma unroll
            for (int q = 0; q < 4; q++) acc[i][j][q] = 0.f;

    uint2 ra[4], rb[4];
    int nk = K / GBK;

#pragma unroll
    for (int i = 0; i < 4; i++) {
        int r = aRow + 32 * i;
        ra[i] = (bm + r < M) ? *(const uint2*)(A + (size_t)(bm + r) * K + aCol)
                             : make_uint2(0u, 0u);
        rb[i] = *(const uint2*)(B + (size_t)(bRow + 8 * i) * FDIM + bn + bCol);
    }

    int a_lrow = lane & 15;
    int a_lcol = (lane >> 4) * 8;
    int g      = lane >> 3;
    int b_lrow = (g & 1) * 8 + (lane & 7);
    int b_lcol = (g >> 1) * 8;

    for (int kt = 0; kt < nk; kt++) {
#pragma unroll
        for (int i = 0; i < 4; i++) {
            *(uint2*)&As[aRow + 32 * i][aCol] = ra[i];
            *(uint2*)&Bs[bRow + 8 * i][bCol] = rb[i];
        }
        __syncthreads();

        if (kt + 1 < nk) {
            int kb = (kt + 1) * GBK;
#pragma unroll
            for (int i = 0; i < 4; i++) {
                int r = aRow + 32 * i;
                ra[i] = (bm + r < M)
                      ? *(const uint2*)(A + (size_t)(bm + r) * K + kb + aCol)
                      : make_uint2(0u, 0u);
                rb[i] = *(const uint2*)(B + (size_t)(kb + bRow + 8 * i) * FDIM + bn + bCol);
            }
        }

#pragma unroll
        for (int kk = 0; kk < GBK; kk += 16) {
            unsigned afr[4][4], bfr[4][2];
#pragma unroll
            for (int mt = 0; mt < 4; mt++) {
                unsigned ad = (unsigned)__cvta_generic_to_shared(
                    &As[wm + mt * 16 + a_lrow][kk + a_lcol]);
                ldsm_x4(afr[mt], ad);
            }
#pragma unroll
            for (int np = 0; np < 2; np++) {
                unsigned btmp[4];
                unsigned bd = (unsigned)__cvta_generic_to_shared(
                    &Bs[kk + b_lrow][wn + np * 16 + b_lcol]);
                ldsm_x4_t(btmp, bd);
                bfr[np * 2 + 0][0] = btmp[0];
                bfr[np * 2 + 0][1] = btmp[1];
                bfr[np * 2 + 1][0] = btmp[2];
                bfr[np * 2 + 1][1] = btmp[3];
            }
#pragma unroll
            for (int mt = 0; mt < 4; mt++)
#pragma unroll
                for (int nt = 0; nt < 4; nt++)
                    mma_f16(acc[mt][nt], afr[mt], bfr[nt]);
        }
        __syncthreads();
    }

    if (mode == 0) {
        float* C = pick_rw(csel, nullptr);
#pragma unroll
        for (int mt = 0; mt < 4; mt++) {
#pragma unroll
            for (int nt = 0; nt < 4; nt++) {
                int r = bm + wm + mt * 16 + (lane >> 2);
                int c = bn + wn + nt * 8 + (lane & 3) * 2;
                if (r < M)
                    *(float2*)(C + (size_t)r * FDIM + c) =
                        make_float2(acc[mt][nt][0], acc[mt][nt][1]);
                if (r + 8 < M)
                    *(float2*)(C + (size_t)(r + 8) * FDIM + c) =
                        make_float2(acc[mt][nt][2], acc[mt][nt][3]);
            }
        }
    } else {
        float asv[8], adv[8];
#pragma unroll
        for (int nt = 0; nt < 4; nt++)
#pragma unroll
            for (int p = 0; p < 2; p++) {
                int c = bn + wn + nt * 8 + (lane & 3) * 2 + p;
                asv[nt * 2 + p] = avS[c];
                adv[nt * 2 + p] = avD[c];
            }

        float s1[8], s2[8];
#pragma unroll
        for (int i = 0; i < 8; i++) { s1[i] = 0.f; s2[i] = 0.f; }

#pragma unroll
        for (int mt = 0; mt < 4; mt++) {
#pragma unroll
            for (int nt = 0; nt < 4; nt++) {
                int r = bm + wm + mt * 16 + (lane >> 2);
                int c = bn + wn + nt * 8 + (lane & 3) * 2;
                if (r < M)
                    *(__half2*)(sc_gh + (size_t)r * FDIM + c) =
                        __floats2half2_rn(acc[mt][nt][0], acc[mt][nt][1]);
                if (r + 8 < M)
                    *(__half2*)(sc_gh + (size_t)(r + 8) * FDIM + c) =
                        __floats2half2_rn(acc[mt][nt][2], acc[mt][nt][3]);
#pragma unroll
                for (int q = 0; q < 4; q++) {
                    int qh = q >> 1, p = q & 1;
                    s1[mt * 2 + qh] += acc[mt][nt][q] * asv[nt * 2 + p];
                    s2[mt * 2 + qh] += acc[mt][nt][q] * adv[nt * 2 + p];
                }
            }
        }
#pragma unroll
        for (int off = 1; off <= 2; off <<= 1)
#pragma unroll
            for (int i = 0; i < 8; i++) {
                s1[i] += __shfl_xor_sync(0xffffffffu, s1[i], off);
                s2[i] += __shfl_xor_sync(0xffffffffu, s2[i], off);
            }
        if ((lane & 3) == 0) {
#pragma unroll
            for (int mt = 0; mt < 4; mt++)
#pragma unroll
                for (int qh = 0; qh < 2; qh++) {
                    int rl = wm + mt * 16 + (lane >> 2) + 8 * qh;
                    atomicAdd(&es_sh[rl], s1[mt * 2 + qh]);
                    atomicAdd(&ed_sh[rl], s2[mt * 2 + qh]);
                }
        }
        __syncthreads();
        if (tid < GBM) {
            int r = bm + tid;
            if (r < M) {
                sc_es[r * NH + blockIdx.x] = es_sh[tid];
                sc_ed[r * NH + blockIdx.x] = ed_sh[tid];
            }
        }
    }
}

// ------- fused softmax + aggregate: 128 thr, warp=head, 2 edges/iter --------
__global__ __launch_bounds__(128) void agg_k(const float* __restrict__ bias,
                                             int rsel,
                                             float* __restrict__ outext,
                                             int osel, int hsel) {
    const float* res = pick_ro(rsel, nullptr);
    float* out = pick_rw(osel, outext);
    __half* outh = (hsel == 1) ? sc_h1h : (hsel == 2) ? sc_h2h : nullptr;

    __shared__ float w_sh[NH][DCAP];
    __shared__ int   idx_sh[DCAP];

    int d = blockIdx.x;
    int w = threadIdx.x >> 5, lane = threadIdx.x & 31;
    int beg = sc_rowptr[d], end = sc_rowptr[d + 1];
    int deg = end - beg;
    float edv = sc_ed[d * NH + w];

    if (deg <= DCAP) {
        // pass 1: leaky scores -> smem, track max
        float m = -INFINITY;
        for (int j = lane; j < deg; j += 32) {
            int s = sc_csr[beg + j];
            if (w == 0) idx_sh[j] = s;
            float e = sc_es[s * NH + w] + edv;
            e = e > 0.f ? e : 0.2f * e;
            w_sh[w][j] = e;
            m = fmaxf(m, e);
        }
#pragma unroll
        for (int o = 16; o; o >>= 1) m = fmaxf(m, __shfl_xor_sync(0xffffffffu, m, o));

        // pass 2: exp in place + denom
        float den = 0.f;
        for (int j = lane; j < deg; j += 32) {
            float ex = __expf(w_sh[w][j] - m);
            w_sh[w][j] = ex;
            den += ex;
        }
#pragma unroll
        for (int o = 16; o; o >>= 1) den += __shfl_xor_sync(0xffffffffu, den, o);
        float inv = 1.f / (den + 1e-16f);

        __syncthreads();

        // pass 3: two edges per iteration (half-warp each), 16B loads
        int hl = lane >> 4;        // 0: even edges, 1: odd edges
        int cl = lane & 15;        // 8-half column group
        const __half* ghp = sc_gh + w * HC + 8 * cl;
        float a0 = 0.f, a1 = 0.f, a2 = 0.f, a3 = 0.f,
              a4 = 0.f, a5 = 0.f, a6 = 0.f, a7 = 0.f;
#pragma unroll 4
        for (int j = hl; j < deg; j += 2) {
            int s = idx_sh[j];
            float wt = w_sh[w][j] * inv;
            uint4 hv = *(const uint4*)(ghp + (size_t)s * FDIM);
            float2 f0 = __half22float2(*(const __half2*)&hv.x);
            float2 f1 = __half22float2(*(const __half2*)&hv.y);
            float2 f2 = __half22float2(*(const __half2*)&hv.z);
            float2 f3 = __half22float2(*(const __half2*)&hv.w);
            a0 += wt * f0.x; a1 += wt * f0.y;
            a2 += wt * f1.x; a3 += wt * f1.y;
            a4 += wt * f2.x; a5 += wt * f2.y;
            a6 += wt * f3.x; a7 += wt * f3.y;
        }
        // merge the two half-warps (same columns, disjoint edge subsets)
        a0 += __shfl_xor_sync(0xffffffffu, a0, 16);
        a1 += __shfl_xor_sync(0xffffffffu, a1, 16);
        a2 += __shfl_xor_sync(0xffffffffu, a2, 16);
        a3 += __shfl_xor_sync(0xffffffffu, a3, 16);
        a4 += __shfl_xor_sync(0xffffffffu, a4, 16);
        a5 += __shfl_xor_sync(0xffffffffu, a5, 16);
        a6 += __shfl_xor_sync(0xffffffffu, a6, 16);
        a7 += __shfl_xor_sync(0xffffffffu, a7, 16);

        if (hl == 0) {
            int c = w * HC + 8 * cl;
            float4 b0 = *(const float4*)(bias + c);
            float4 b1 = *(const float4*)(bias + c + 4);
            float4 r0 = *(const float4*)(res + (size_t)d * FDIM + c);
            float4 r1 = *(const float4*)(res + (size_t)d * FDIM + c + 4);
            float4 o0, o1;
            o0.x = fmaxf(a0 + b0.x + r0.x, 0.f);
            o0.y = fmaxf(a1 + b0.y + r0.y, 0.f);
            o0.z = fmaxf(a2 + b0.z + r0.z, 0.f);
            o0.w = fmaxf(a3 + b0.w + r0.w, 0.f);
            o1.x = fmaxf(a4 + b1.x + r1.x, 0.f);
            o1.y = fmaxf(a5 + b1.y + r1.y, 0.f);
            o1.z = fmaxf(a6 + b1.z + r1.z, 0.f);
            o1.w = fmaxf(a7 + b1.w + r1.w, 0.f);
            *(float4*)(out + (size_t)d * FDIM + c) = o0;
            *(float4*)(out + (size_t)d * FDIM + c + 4) = o1;
            if (outh) {
                uint4 hv;
                *(__half2*)&hv.x = __floats2half2_rn(o0.x, o0.y);
                *(__half2*)&hv.y = __floats2half2_rn(o0.z, o0.w);
                *(__half2*)&hv.z = __floats2half2_rn(o1.x, o1.y);
                *(__half2*)&hv.w = __floats2half2_rn(o1.z, o1.w);
                *(uint4*)(outh + (size_t)d * FDIM + c) = hv;
            }
        }
    } else {
        // fallback (deg > DCAP): round-11 style full-warp path
        float m = -INFINITY;
        for (int j = beg + lane; j < end; j += 32) {
            int s = sc_csr[j];
            float e = sc_es[s * NH + w] + edv;
            e = e > 0.f ? e : 0.2f * e;
            m = fmaxf(m, e);
        }
#pragma unroll
        for (int o = 16; o; o >>= 1) m = fmaxf(m, __shfl_xor_sync(0xffffffffu, m, o));
        float den = 0.f;
        for (int j = beg + lane; j < end; j += 32) {
            int s = sc_csr[j];
            float e = sc_es[s * NH + w] + edv;
            e = e > 0.f ? e : 0.2f * e;
            den += __expf(e - m);
        }
#pragma unroll
        for (int o = 16; o; o >>= 1) den += __shfl_xor_sync(0xffffffffu, den, o);
        float inv = 1.f / (den + 1e-16f);

        float4 acc = make_float4(0.f, 0.f, 0.f, 0.f);
        const __half* ghp = sc_gh + w * HC + 4 * lane;
        for (int j = beg; j < end; j++) {
            int s = sc_csr[j];
            float e = sc_es[s * NH + w] + edv;
            e = e > 0.f ? e : 0.2f * e;
            float wt = __expf(e - m) * inv;
            uint2 hv = *(const uint2*)(ghp + (size_t)s * FDIM);
            float2 f0 = __half22float2(*(const __half2*)&hv.x);
            float2 f1 = __half22float2(*(const __half2*)&hv.y);
            acc.x += wt * f0.x;
            acc.y += wt * f0.y;
            acc.z += wt * f1.x;
            acc.w += wt * f1.y;
        }
        int c = w * HC + 4 * lane;
        float4 bv = *(const float4*)(bias + c);
        float4 rv = *(const float4*)(res + (size_t)d * FDIM + c);
        float4 o;
        o.x = fmaxf(acc.x + bv.x + rv.x, 0.f);
        o.y = fmaxf(acc.y + bv.y + rv.y, 0.f);
        o.z = fmaxf(acc.z + bv.z + rv.z, 0.f);
        o.w = fmaxf(acc.w + bv.w + rv.w, 0.f);
        *(float4*)(out + (size_t)d * FDIM + c) = o;
        if (outh) {
            uint2 hv;
            *(__half2*)&hv.x = __floats2half2_rn(o.x, o.y);
            *(__half2*)&hv.y = __floats2half2_rn(o.z, o.w);
            *(uint2*)(outh + (size_t)d * FDIM + c) = hv;
        }
    }
}

// ---------------- host orchestration ----------------------------------------
extern "C" void kernel_launch(void* const* d_in, const int* in_sizes, int n_in,
                              void* d_out, int out_size) {
    const float* x       = (const float*)d_in[0];
    const void* ei       = d_in[1];
    const float* w0      = (const float*)d_in[2];
    const float* b0      = (const float*)d_in[3];
    const float* asrc0   = (const float*)d_in[4];
    const float* adst0   = (const float*)d_in[5];
    const float* res_w0  = (const float*)d_in[6];
    const float* w1      = (const float*)d_in[7];
    const float* b1      = (const float*)d_in[8];
    const float* asrc1   = (const float*)d_in[9];
    const float* adst1   = (const float*)d_in[10];
    const float* w2      = (const float*)d_in[11];
    const float* b2      = (const float*)d_in[12];
    const float* asrc2   = (const float*)d_in[13];
    const float* adst2   = (const float*)d_in[14];
    float* out           = (float*)d_out;

    int E = in_sizes[1] / 2;

    static cudaStream_t s2 = nullptr;
    static cudaEvent_t evFork = nullptr, evJoin = nullptr;
    if (s2 == nullptr) {
        cudaStreamCreateWithFlags(&s2, cudaStreamNonBlocking);
        cudaEventCreateWithFlags(&evFork, cudaEventDisableTiming);
        cudaEventCreateWithFlags(&evJoin, cudaEventDisableTiming);
    }

    cudaEventRecord(evFork, 0);
    cudaStreamWaitEvent(s2, evFork, 0);
    detect_k<<<1, 1, 0, s2>>>(ei);
    init_deg_k<<<(NN + 255) / 256, 256, 0, s2>>>();
    hist_k<<<(E + 255) / 256, 256, 0, s2>>>(ei, E);
    scan_k<<<1, 1024, 0, s2>>>();
    scatter_k<<<(E + NN + 255) / 256, 256, 0, s2>>>(ei, E);
    cudaEventRecord(evJoin, s2);

    cvt_x_k<<<2048, 256>>>(x);
    cvt_w_k<<<1024, 256>>>(w0, res_w0, w1, w2);

    dim3 ggrid(FDIM / GBN, (NN + GBM - 1) / GBM);

    tgemm_k<<<ggrid, 256>>>(0, OFF_W0, 0, 1, asrc0, adst0, NN, 256);
    tgemm_k<<<ggrid, 256>>>(0, OFF_RW0, 2, 0, nullptr, nullptr, NN, 256);

    cudaStreamWaitEvent(0, evJoin, 0);
    agg_k<<<NN, 128>>>(b0, /*res=*/2, nullptr, /*out=*/1, /*h=*/1);

    tgemm_k<<<ggrid, 256>>>(1, OFF_W1, 0, 1, asrc1, adst1, NN, 512);
    agg_k<<<NN, 128>>>(b1, /*res=*/1, nullptr, /*out=*/2, /*h=*/2);

    tgemm_k<<<ggrid, 256>>>(2, OFF_W2, 0, 1, asrc2, adst2, NN, 512);
    agg_k<<<NN, 128>>>(b2, /*res=*/2, out, /*out=*/0, /*h=*/0);
}

// round 17
// speedup vs baseline: 1.2778x; 1.1521x over previous
#include <cuda_runtime.h>
#include <cuda_fp16.h>
#include <math.h>

#define NN   20000
#define EMAX 320000
#define FDIM 512
#define NH   4
#define HC   128
#define DCAP 256

#define OFF_W0   0
#define OFF_RW0  131072
#define OFF_W1   262144
#define OFF_W2   524288
#define WH_TOT   786432

// ---------------- scratch ----------------------------------------------------
__device__ __half sc_gh[(size_t)NN * FDIM];   // projected features g (fp16)
__device__ __half sc_xh[(size_t)NN * 256];    // x fp16
__device__ __half sc_h1h[(size_t)NN * FDIM];  // h1 fp16
__device__ __half sc_h2h[(size_t)NN * FDIM];  // res0 / h2 fp16
__device__ __half sc_wh[WH_TOT];              // weights fp16
__device__ float  sc_es[NN * NH];
__device__ float  sc_ed[NN * NH];
__device__ int    sc_deg[NN];
__device__ int    sc_rowptr[NN + 1];
__device__ int    sc_cursor[NN];
__device__ int    sc_csr[EMAX + NN];
__device__ int    sc_is64;

__device__ __forceinline__ const __half* pick_ah(int sel) {
    if (sel == 0) return sc_xh;
    if (sel == 1) return sc_h1h;
    return sc_h2h;
}
__device__ __forceinline__ __half* pick_h(int sel) {
    if (sel == 1) return sc_h1h;
    return sc_h2h;
}
__device__ __forceinline__ int load_edge(const void* ei, size_t idx) {
    if (sc_is64) return (int)((const long long*)ei)[idx];
    return ((const int*)ei)[idx];
}

// ---------------- dtype probe -------------------------------------------------
__global__ void detect_k(const void* ei) {
    const int* p = (const int*)ei;
    int any = 0;
#pragma unroll 8
    for (int i = 0; i < 256; i++) any |= p[2 * i + 1];
    sc_is64 = (any == 0) ? 1 : 0;
}

// ---------------- fp32 -> fp16 conversion -------------------------------------
__global__ void cvt_x_k(const float* __restrict__ x) {
    int stride = gridDim.x * blockDim.x;
    for (int i = blockIdx.x * blockDim.x + threadIdx.x; i < NN * 128; i += stride) {
        float2 v = *(const float2*)(x + 2 * (size_t)i);
        *(__half2*)(sc_xh + 2 * (size_t)i) = __floats2half2_rn(v.x, v.y);
    }
}
__global__ void cvt_w_k(const float* __restrict__ w0, const float* __restrict__ rw0,
                        const float* __restrict__ w1, const float* __restrict__ w2) {
    int stride = gridDim.x * blockDim.x;
    for (int i = blockIdx.x * blockDim.x + threadIdx.x; i < WH_TOT / 2; i += stride) {
        int e = 2 * i;
        float2 v;
        if (e < OFF_RW0)      v = *(const float2*)(w0 + e);
        else if (e < OFF_W1)  v = *(const float2*)(rw0 + (e - OFF_RW0));
        else if (e < OFF_W2)  v = *(const float2*)(w1 + (e - OFF_W1));
        else                  v = *(const float2*)(w2 + (e - OFF_W2));
        *(__half2*)(sc_wh + e) = __floats2half2_rn(v.x, v.y);
    }
}

// ---------------- CSR build ---------------------------------------------------
__global__ void init_deg_k() {
    int i = blockIdx.x * blockDim.x + threadIdx.x;
    if (i < NN) sc_deg[i] = 1;
}
__global__ void hist_k(const void* ei, int E) {
    int e = blockIdx.x * blockDim.x + threadIdx.x;
    if (e < E) atomicAdd(&sc_deg[load_edge(ei, (size_t)E + e)], 1);
}
__global__ void scan_k() {
    __shared__ int sums[1024];
    const int CH = 20;
    int t = threadIdx.x;
    int base = t * CH;
    int local[CH];
    int s = 0;
#pragma unroll
    for (int i = 0; i < CH; i++) {
        int idx = base + i;
        int v = (idx < NN) ? sc_deg[idx] : 0;
        local[i] = s;
        s += v;
    }
    sums[t] = s;
    __syncthreads();
    for (int off = 1; off < 1024; off <<= 1) {
        int v = (t >= off) ? sums[t - off] : 0;
        __syncthreads();
        sums[t] += v;
        __syncthreads();
    }
    int offset = (t == 0) ? 0 : sums[t - 1];
#pragma unroll
    for (int i = 0; i < CH; i++) {
        int idx = base + i;
        if (idx < NN) {
            int r = offset + local[i];
            sc_rowptr[idx] = r;
            sc_cursor[idx] = r;
        }
    }
    if (t == 1023) sc_rowptr[NN] = sums[1023];
}
__global__ void scatter_k(const void* ei, int E) {
    int i = blockIdx.x * blockDim.x + threadIdx.x;
    if (i < E) {
        int d = load_edge(ei, (size_t)E + i);
        int s = load_edge(ei, i);
        sc_csr[atomicAdd(&sc_cursor[d], 1)] = s;
    } else if (i < E + NN) {
        int v = i - E;
        sc_csr[atomicAdd(&sc_cursor[v], 1)] = v;
    }
}

// ---------------- FP16 GEMM (round-11 proven: ld+sts+ldmatrix) ---------------
#define GBM 128
#define GBN 128
#define GBK 32
#define AH_LD 40
#define BH_LD 136

__device__ __forceinline__ void mma_f16(float* d, const unsigned* a, const unsigned* b) {
    asm volatile(
        "mma.sync.aligned.m16n8k16.row.col.f32.f16.f16.f32 "
        "{%0,%1,%2,%3}, {%4,%5,%6,%7}, {%8,%9}, {%0,%1,%2,%3};"
        : "+f"(d[0]), "+f"(d[1]), "+f"(d[2]), "+f"(d[3])
        : "r"(a[0]), "r"(a[1]), "r"(a[2]), "r"(a[3]), "r"(b[0]), "r"(b[1]));
}
__device__ __forceinline__ void ldsm_x4(unsigned* r, unsigned addr) {
    asm volatile("ldmatrix.sync.aligned.m8n8.x4.shared.b16 {%0,%1,%2,%3}, [%4];"
                 : "=r"(r[0]), "=r"(r[1]), "=r"(r[2]), "=r"(r[3]) : "r"(addr));
}
__device__ __forceinline__ void ldsm_x4_t(unsigned* r, unsigned addr) {
    asm volatile("ldmatrix.sync.aligned.m8n8.x4.trans.shared.b16 {%0,%1,%2,%3}, [%4];"
                 : "=r"(r[0]), "=r"(r[1]), "=r"(r[2]), "=r"(r[3]) : "r"(addr));
}

// mode 0: fp16 C -> sc_h2h (residual GEMM)
// mode 1: sc_gh fp16 = A@B + fused scores
__global__ __launch_bounds__(256, 1) void tgemm_k(int asel, int woff,
                                                  int mode,
                                                  const float* __restrict__ avS,
                                                  const float* __restrict__ avD,
                                                  int M, int K) {
    const __half* A = pick_ah(asel);
    const __half* B = sc_wh + woff;

    __shared__ __half As[GBM][AH_LD];
    __shared__ __half Bs[GBK][BH_LD];
    __shared__ float es_sh[GBM];
    __shared__ float ed_sh[GBM];

    int tid  = threadIdx.x;
    int lane = tid & 31;
    int warp = tid >> 5;
    int wm = (warp >> 2) * 64;
    int wn = (warp & 3) * 32;
    int bm = blockIdx.y * GBM;
    int bn = blockIdx.x * GBN;

    if (mode && tid < GBM) { es_sh[tid] = 0.f; ed_sh[tid] = 0.f; }

    int aRow = tid >> 3;
    int aCol = (tid & 7) * 4;
    int bRow = tid >> 5;
    int bCol = (tid & 31) * 4;

    float acc[4][4][4];
#pragma unroll
    for (int i = 0; i < 4; i++)
#pragma unroll
        for (int j = 0; j < 4; j++)
#pragma unroll
            for (int q = 0; q < 4; q++) acc[i][j][q] = 0.f;

    uint2 ra[4], rb[4];
    int nk = K / GBK;

#pragma unroll
    for (int i = 0; i < 4; i++) {
        int r = aRow + 32 * i;
        ra[i] = (bm + r < M) ? *(const uint2*)(A + (size_t)(bm + r) * K + aCol)
                             : make_uint2(0u, 0u);
        rb[i] = *(const uint2*)(B + (size_t)(bRow + 8 * i) * FDIM + bn + bCol);
    }

    int a_lrow = lane & 15;
    int a_lcol = (lane >> 4) * 8;
    int g      = lane >> 3;
    int b_lrow = (g & 1) * 8 + (lane & 7);
    int b_lcol = (g >> 1) * 8;

    for (int kt = 0; kt < nk; kt++) {
#pragma unroll
        for (int i = 0; i < 4; i++) {
            *(uint2*)&As[aRow + 32 * i][aCol] = ra[i];
            *(uint2*)&Bs[bRow + 8 * i][bCol] = rb[i];
        }
        __syncthreads();

        if (kt + 1 < nk) {
            int kb = (kt + 1) * GBK;
#pragma unroll
            for (int i = 0; i < 4; i++) {
                int r = aRow + 32 * i;
                ra[i] = (bm + r < M)
                      ? *(const uint2*)(A + (size_t)(bm + r) * K + kb + aCol)
                      : make_uint2(0u, 0u);
                rb[i] = *(const uint2*)(B + (size_t)(kb + bRow + 8 * i) * FDIM + bn + bCol);
            }
        }

#pragma unroll
        for (int kk = 0; kk < GBK; kk += 16) {
            unsigned afr[4][4], bfr[4][2];
#pragma unroll
            for (int mt = 0; mt < 4; mt++) {
                unsigned ad = (unsigned)__cvta_generic_to_shared(
                    &As[wm + mt * 16 + a_lrow][kk + a_lcol]);
                ldsm_x4(afr[mt], ad);
            }
#pragma unroll
            for (int np = 0; np < 2; np++) {
                unsigned btmp[4];
                unsigned bd = (unsigned)__cvta_generic_to_shared(
                    &Bs[kk + b_lrow][wn + np * 16 + b_lcol]);
                ldsm_x4_t(btmp, bd);
                bfr[np * 2 + 0][0] = btmp[0];
                bfr[np * 2 + 0][1] = btmp[1];
                bfr[np * 2 + 1][0] = btmp[2];
                bfr[np * 2 + 1][1] = btmp[3];
            }
#pragma unroll
            for (int mt = 0; mt < 4; mt++)
#pragma unroll
                for (int nt = 0; nt < 4; nt++)
                    mma_f16(acc[mt][nt], afr[mt], bfr[nt]);
        }
        __syncthreads();
    }

    if (mode == 0) {
        // residual GEMM: fp16 store to sc_h2h
#pragma unroll
        for (int mt = 0; mt < 4; mt++) {
#pragma unroll
            for (int nt = 0; nt < 4; nt++) {
                int r = bm + wm + mt * 16 + (lane >> 2);
                int c = bn + wn + nt * 8 + (lane & 3) * 2;
                if (r < M)
                    *(__half2*)(sc_h2h + (size_t)r * FDIM + c) =
                        __floats2half2_rn(acc[mt][nt][0], acc[mt][nt][1]);
                if (r + 8 < M)
                    *(__half2*)(sc_h2h + (size_t)(r + 8) * FDIM + c) =
                        __floats2half2_rn(acc[mt][nt][2], acc[mt][nt][3]);
            }
        }
    } else {
        float asv[8], adv[8];
#pragma unroll
        for (int nt = 0; nt < 4; nt++)
#pragma unroll
            for (int p = 0; p < 2; p++) {
                int c = bn + wn + nt * 8 + (lane & 3) * 2 + p;
                asv[nt * 2 + p] = avS[c];
                adv[nt * 2 + p] = avD[c];
            }

        float s1[8], s2[8];
#pragma unroll
        for (int i = 0; i < 8; i++) { s1[i] = 0.f; s2[i] = 0.f; }

#pragma unroll
        for (int mt = 0; mt < 4; mt++) {
#pragma unroll
            for (int nt = 0; nt < 4; nt++) {
                int r = bm + wm + mt * 16 + (lane >> 2);
                int c = bn + wn + nt * 8 + (lane & 3) * 2;
                if (r < M)
                    *(__half2*)(sc_gh + (size_t)r * FDIM + c) =
                        __floats2half2_rn(acc[mt][nt][0], acc[mt][nt][1]);
                if (r + 8 < M)
                    *(__half2*)(sc_gh + (size_t)(r + 8) * FDIM + c) =
                        __floats2half2_rn(acc[mt][nt][2], acc[mt][nt][3]);
#pragma unroll
                for (int q = 0; q < 4; q++) {
                    int qh = q >> 1, p = q & 1;
                    s1[mt * 2 + qh] += acc[mt][nt][q] * asv[nt * 2 + p];
                    s2[mt * 2 + qh] += acc[mt][nt][q] * adv[nt * 2 + p];
                }
            }
        }
#pragma unroll
        for (int off = 1; off <= 2; off <<= 1)
#pragma unroll
            for (int i = 0; i < 8; i++) {
                s1[i] += __shfl_xor_sync(0xffffffffu, s1[i], off);
                s2[i] += __shfl_xor_sync(0xffffffffu, s2[i], off);
            }
        if ((lane & 3) == 0) {
#pragma unroll
            for (int mt = 0; mt < 4; mt++)
#pragma unroll
                for (int qh = 0; qh < 2; qh++) {
                    int rl = wm + mt * 16 + (lane >> 2) + 8 * qh;
                    atomicAdd(&es_sh[rl], s1[mt * 2 + qh]);
                    atomicAdd(&ed_sh[rl], s2[mt * 2 + qh]);
                }
        }
        __syncthreads();
        if (tid < GBM) {
            int r = bm + tid;
            if (r < M) {
                sc_es[r * NH + blockIdx.x] = es_sh[tid];
                sc_ed[r * NH + blockIdx.x] = ed_sh[tid];
            }
        }
    }
}

// ------- fused softmax + aggregate (round-11 loop; fp16 res, fp16/fp32 out) --
__global__ __launch_bounds__(128) void agg_k(const float* __restrict__ bias,
                                             int rsel,
                                             float* __restrict__ outext,
                                             int osel) {
    const __half* resh = pick_ah(rsel);      // 1=h1h, 2=h2h
    __half* outh = (osel != 0) ? pick_h(osel) : nullptr;

    __shared__ float w_sh[NH][DCAP];
    __shared__ int   idx_sh[DCAP];

    int d = blockIdx.x;
    int w = threadIdx.x >> 5, lane = threadIdx.x & 31;
    int beg = sc_rowptr[d], end = sc_rowptr[d + 1];
    int deg = end - beg;
    float edv = sc_ed[d * NH + w];

    float4 acc = make_float4(0.f, 0.f, 0.f, 0.f);
    const __half* ghp = sc_gh + w * HC + 4 * lane;

    if (deg <= DCAP) {
        float m = -INFINITY;
        for (int j = lane; j < deg; j += 32) {
            int s = sc_csr[beg + j];
            if (w == 0) idx_sh[j] = s;
            float e = sc_es[s * NH + w] + edv;
            e = e > 0.f ? e : 0.2f * e;
            w_sh[w][j] = e;
            m = fmaxf(m, e);
        }
#pragma unroll
        for (int o = 16; o; o >>= 1) m = fmaxf(m, __shfl_xor_sync(0xffffffffu, m, o));

        float den = 0.f;
        for (int j = lane; j < deg; j += 32) {
            float ex = __expf(w_sh[w][j] - m);
            w_sh[w][j] = ex;
            den += ex;
        }
#pragma unroll
        for (int o = 16; o; o >>= 1) den += __shfl_xor_sync(0xffffffffu, den, o);
        float inv = 1.f / (den + 1e-16f);

        __syncthreads();

#pragma unroll 4
        for (int j = 0; j < deg; j++) {
            int s = idx_sh[j];
            float wt = w_sh[w][j] * inv;
            uint2 hv = *(const uint2*)(ghp + (size_t)s * FDIM);
            float2 f0 = __half22float2(*(const __half2*)&hv.x);
            float2 f1 = __half22float2(*(const __half2*)&hv.y);
            acc.x += wt * f0.x;
            acc.y += wt * f0.y;
            acc.z += wt * f1.x;
            acc.w += wt * f1.y;
        }
    } else {
        float m = -INFINITY;
        for (int j = beg + lane; j < end; j += 32) {
            int s = sc_csr[j];
            float e = sc_es[s * NH + w] + edv;
            e = e > 0.f ? e : 0.2f * e;
            m = fmaxf(m, e);
        }
#pragma unroll
        for (int o = 16; o; o >>= 1) m = fmaxf(m, __shfl_xor_sync(0xffffffffu, m, o));
        float den = 0.f;
        for (int j = beg + lane; j < end; j += 32) {
            int s = sc_csr[j];
            float e = sc_es[s * NH + w] + edv;
            e = e > 0.f ? e : 0.2f * e;
            den += __expf(e - m);
        }
#pragma unroll
        for (int o = 16; o; o >>= 1) den += __shfl_xor_sync(0xffffffffu, den, o);
        float inv = 1.f / (den + 1e-16f);
        for (int j = beg; j < end; j++) {
            int s = sc_csr[j];
            float e = sc_es[s * NH + w] + edv;
            e = e > 0.f ? e : 0.2f * e;
            float wt = __expf(e - m) * inv;
            uint2 hv = *(const uint2*)(ghp + (size_t)s * FDIM);
            float2 f0 = __half22float2(*(const __half2*)&hv.x);
            float2 f1 = __half22float2(*(const __half2*)&hv.y);
            acc.x += wt * f0.x;
            acc.y += wt * f0.y;
            acc.z += wt * f1.x;
            acc.w += wt * f1.y;
        }
    }

    int c = w * HC + 4 * lane;
    float4 bv = *(const float4*)(bias + c);
    uint2 rh = *(const uint2*)(resh + (size_t)d * FDIM + c);
    float2 r0 = __half22float2(*(const __half2*)&rh.x);
    float2 r1 = __half22float2(*(const __half2*)&rh.y);
    float4 o;
    o.x = fmaxf(acc.x + bv.x + r0.x, 0.f);
    o.y = fmaxf(acc.y + bv.y + r0.y, 0.f);
    o.z = fmaxf(acc.z + bv.z + r1.x, 0.f);
    o.w = fmaxf(acc.w + bv.w + r1.y, 0.f);
    if (osel == 0) {
        *(float4*)(outext + (size_t)d * FDIM + c) = o;
    } else {
        uint2 hv;
        *(__half2*)&hv.x = __floats2half2_rn(o.x, o.y);
        *(__half2*)&hv.y = __floats2half2_rn(o.z, o.w);
        *(uint2*)(outh + (size_t)d * FDIM + c) = hv;
    }
}

// ---------------- host orchestration ----------------------------------------
extern "C" void kernel_launch(void* const* d_in, const int* in_sizes, int n_in,
                              void* d_out, int out_size) {
    const float* x       = (const float*)d_in[0];
    const void* ei       = d_in[1];
    const float* w0      = (const float*)d_in[2];
    const float* b0      = (const float*)d_in[3];
    const float* asrc0   = (const float*)d_in[4];
    const float* adst0   = (const float*)d_in[5];
    const float* res_w0  = (const float*)d_in[6];
    const float* w1      = (const float*)d_in[7];
    const float* b1      = (const float*)d_in[8];
    const float* asrc1   = (const float*)d_in[9];
    const float* adst1   = (const float*)d_in[10];
    const float* w2      = (const float*)d_in[11];
    const float* b2      = (const float*)d_in[12];
    const float* asrc2   = (const float*)d_in[13];
    const float* adst2   = (const float*)d_in[14];
    float* out           = (float*)d_out;

    int E = in_sizes[1] / 2;

    static cudaStream_t s2 = nullptr;
    static cudaEvent_t evFork = nullptr, evJoin = nullptr;
    if (s2 == nullptr) {
        cudaStreamCreateWithFlags(&s2, cudaStreamNonBlocking);
        cudaEventCreateWithFlags(&evFork, cudaEventDisableTiming);
        cudaEventCreateWithFlags(&evJoin, cudaEventDisableTiming);
    }

    cudaEventRecord(evFork, 0);
    cudaStreamWaitEvent(s2, evFork, 0);
    detect_k<<<1, 1, 0, s2>>>(ei);
    init_deg_k<<<(NN + 255) / 256, 256, 0, s2>>>();
    hist_k<<<(E + 255) / 256, 256, 0, s2>>>(ei, E);
    scan_k<<<1, 1024, 0, s2>>>();
    scatter_k<<<(E + NN + 255) / 256, 256, 0, s2>>>(ei, E);
    cudaEventRecord(evJoin, s2);

    cvt_x_k<<<2048, 256>>>(x);
    cvt_w_k<<<1024, 256>>>(w0, res_w0, w1, w2);

    dim3 ggrid(FDIM / GBN, (NN + GBM - 1) / GBM);

    // layer 0: proj (gh + scores); residual fp16 -> sc_h2h
    tgemm_k<<<ggrid, 256>>>(0, OFF_W0, 1, asrc0, adst0, NN, 256);
    tgemm_k<<<ggrid, 256>>>(0, OFF_RW0, 0, nullptr, nullptr, NN, 256);

    cudaStreamWaitEvent(0, evJoin, 0);
    agg_k<<<NN, 128>>>(b0, /*res=*/2, nullptr, /*out=*/1);   // h1 -> sc_h1h

    tgemm_k<<<ggrid, 256>>>(1, OFF_W1, 1, asrc1, adst1, NN, 512);
    agg_k<<<NN, 128>>>(b1, /*res=*/1, nullptr, /*out=*/2);   // h2 -> sc_h2h

    tgemm_k<<<ggrid, 256>>>(2, OFF_W2, 1, asrc2, adst2, NN, 512);
    agg_k<<<NN, 128>>>(b2, /*res=*/2, out, /*out=*/0);       // fp32 final
}